// round 3
// baseline (speedup 1.0000x reference)
#include <cuda_runtime.h>
#include <cuda_bf16.h>

#define FRAME_L   1024
#define HOP       256
#define MAXNF     33024   // >= 32765, padded

// Scratch (no cudaMalloc allowed): per-frame params.
// g_params[f] = {scale (<0 means invalid/unvoiced), new_len as float}
__device__ float2 g_params[MAXNF];

__global__ void psola_init_kernel(const float* __restrict__ src_f0,
                                  const float* __restrict__ tgt_f0,
                                  const int* __restrict__ voiced,
                                  int nf)
{
    int i = blockIdx.x * blockDim.x + threadIdx.x;
    if (i < nf) {
        float s = src_f0[i];
        float t = tgt_f0[i];
        bool valid = (voiced[i] != 0) && (s >= 1.0f) && (t >= 1.0f);
        float denom = (t >= 1.0f) ? t : 1.0f;
        float ratio = fminf(fmaxf(s / denom, 0.25f), 4.0f);
        // jnp.round is round-half-to-even -> rintf (device default RN mode)
        float nl = fmaxf(1.0f, rintf((float)FRAME_L * ratio));
        float scale = (float)FRAME_L / nl;
        float2 p;
        p.x = valid ? scale : -1.0f;
        p.y = nl;
        g_params[i] = p;
    }
}

// Each thread produces 4 consecutive output samples (aligned float4).
// The 4 samples share the same covering-frame set {fmax-0..fmax-3}.
// Hann weights computed via one sincosf per sample position:
//   h[j + 256k] = 0.5 - 0.5*cos(theta + k*pi/2)
//              -> {0.5-0.5c, 0.5+0.5s, 0.5+0.5c, 0.5-0.5s}
__global__ void __launch_bounds__(256)
psola_main_kernel(const float* __restrict__ wav,
                  float* __restrict__ out,
                  int T, int nf)
{
    int t4 = (blockIdx.x * blockDim.x + threadIdx.x) << 2;
    if (t4 >= T) return;

    float4 wt4 = *reinterpret_cast<const float4*>(wav + t4);
    float wt[4] = {wt4.x, wt4.y, wt4.z, wt4.w};

    int fmax = t4 >> 8;          // floor(t/HOP)
    int jb   = t4 & 255;         // t mod HOP

    // Load per-frame params once (mostly warp-uniform -> broadcast).
    float scale_k[4], nlen_k[4];
    bool  inr[4], voiced_k[4];
    #pragma unroll
    for (int k = 0; k < 4; k++) {
        int f = fmax - k;
        inr[k] = (f >= 0) & (f < nf);
        float2 p = inr[k] ? g_params[f] : make_float2(-1.0f, 1.0f);
        voiced_k[k] = (p.x >= 0.0f);
        scale_k[k]  = p.x;
        nlen_k[k]   = p.y;
    }

    // Hann weights: one sincosf per sample position i -> all 4 frame phases.
    float h[4][4];   // h[i][k]
    const float TWO_PI_OVER_L = 6.28318530717958647692f / (float)FRAME_L;
    #pragma unroll
    for (int i = 0; i < 4; i++) {
        float s, c;
        sincosf((float)(jb + i) * TWO_PI_OVER_L, &s, &c);
        h[i][0] = fmaf(-0.5f, c, 0.5f);
        h[i][1] = fmaf( 0.5f, s, 0.5f);
        h[i][2] = fmaf( 0.5f, c, 0.5f);
        h[i][3] = fmaf(-0.5f, s, 0.5f);
    }

    float acc[4] = {0.f, 0.f, 0.f, 0.f};
    float ws[4]  = {0.f, 0.f, 0.f, 0.f};

    #pragma unroll
    for (int k = 0; k < 4; k++) {
        if (!inr[k]) continue;
        const float* __restrict__ fr = wav + ((fmax - k) << 8);
        int   j0    = jb + (k << 8);
        float scale = scale_k[k];
        float nlen  = nlen_k[k];
        bool  vo    = voiced_k[k];

        #pragma unroll
        for (int i = 0; i < 4; i++) {
            float hw = h[i][k];
            ws[i] += hw;
            float c;
            if (!vo) {
                c = wt[i];          // passthrough: frames[f][j] == wav[t]
            } else {
                int j = j0 + i;
                float x  = fminf(fmaxf(fmaf((float)j + 0.5f, scale, -0.5f), 0.0f),
                                 (float)(FRAME_L - 1));
                int   x0 = __float2int_rd(x);
                float w  = x - (float)x0;
                int   x1 = min(x0 + 1, FRAME_L - 1);
                float a  = __ldg(fr + x0);
                float b  = __ldg(fr + x1);
                float v  = fmaf(b - a, w, a);   // a*(1-w)+b*w
                c = ((float)j < nlen) ? v : 0.0f;
            }
            acc[i] = fmaf(c, hw, acc[i]);
        }
    }

    float4 r;
    r.x = (ws[0] > 1e-8f) ? acc[0] / ws[0] : acc[0];
    r.y = (ws[1] > 1e-8f) ? acc[1] / ws[1] : acc[1];
    r.z = (ws[2] > 1e-8f) ? acc[2] / ws[2] : acc[2];
    r.w = (ws[3] > 1e-8f) ? acc[3] / ws[3] : acc[3];
    *reinterpret_cast<float4*>(out + t4) = r;
}

extern "C" void kernel_launch(void* const* d_in, const int* in_sizes, int n_in,
                              void* d_out, int out_size)
{
    const float* wav    = (const float*)d_in[0];
    const float* src_f0 = (const float*)d_in[1];
    const float* tgt_f0 = (const float*)d_in[2];
    const int*   voiced = (const int*)d_in[3];
    float* out = (float*)d_out;

    int T  = in_sizes[0];
    int nf_cap = (T - FRAME_L) / HOP + 1;
    int nf = in_sizes[1] < nf_cap ? in_sizes[1] : nf_cap;
    if (nf > MAXNF) nf = MAXNF;

    {
        int threads = 256;
        int blocks = (nf + threads - 1) / threads;
        psola_init_kernel<<<blocks, threads>>>(src_f0, tgt_f0, voiced, nf);
    }
    {
        int threads = 256;
        int n4 = (T + 3) / 4;
        int blocks = (n4 + threads - 1) / threads;
        psola_main_kernel<<<blocks, threads>>>(wav, out, T, nf);
    }
}